// round 1
// baseline (speedup 1.0000x reference)
#include <cuda_runtime.h>
#include <math.h>

#define T_TOK 4096
#define H_DIM 1024
#define I_DIM 2048
#define E_NUM 8
#define K_TOP 2
#define MAXP (T_TOK * K_TOP)  /* 8192 total (token,k) pairs */

// ---- static device scratch (no dynamic allocation allowed) ----
__device__ int   g_count[E_NUM];
__device__ int   g_offset[E_NUM];
__device__ int   g_tok [E_NUM * MAXP];   // token index per (expert, slot)
__device__ float g_gate[E_NUM * MAXP];   // routing weight per (expert, slot)
__device__ float g_h[MAXP * I_DIM];      // 64MB intermediate gelu(x@Wfc) rows, compacted

// ============================================================
// Routing: bucket 8192 (token,k) pairs by expert. One block.
// ============================================================
__global__ void route_kernel(const float* __restrict__ rw,
                             const int*   __restrict__ sel) {
    __shared__ int sc[E_NUM];
    int tid = threadIdx.x;
    if (tid < E_NUM) sc[tid] = 0;
    __syncthreads();
    for (int p = tid; p < T_TOK * K_TOP; p += blockDim.x) {
        int e = sel[p];
        int slot = atomicAdd(&sc[e], 1);
        g_tok [e * MAXP + slot] = p / K_TOP;
        g_gate[e * MAXP + slot] = rw[p];
    }
    __syncthreads();
    if (tid == 0) {
        int off = 0;
        for (int e = 0; e < E_NUM; e++) {
            g_count[e]  = sc[e];
            g_offset[e] = off;
            off += sc[e];
        }
    }
}

__device__ __forceinline__ float gelu_exact(float v) {
    return 0.5f * v * (1.0f + erff(v * 0.7071067811865476f));
}

// ============================================================
// FC: h[off+r, :] = gelu( x[tok(r), :] @ Wfc[e] )
// Tile 64x64x16, 256 threads, 4x4 micro-tile per thread.
// grid = (I/64, MAXP/64, E); inactive tiles exit on count check.
// ============================================================
__global__ __launch_bounds__(256)
void fc_kernel(const float* __restrict__ x,
               const float* __restrict__ wfc) {
    const int e    = blockIdx.z;
    const int cnt  = g_count[e];
    const int row0 = blockIdx.y * 64;
    if (row0 >= cnt) return;
    const int col0 = blockIdx.x * 64;
    const int off  = g_offset[e];

    __shared__ float As[16][64];
    __shared__ float Bs[16][64];
    __shared__ int   stok[64];

    const int tid = threadIdx.x;
    if (tid < 64) {
        int r = row0 + tid;
        if (r >= cnt) r = cnt - 1;          // clamp (valid: row0 < cnt)
        stok[tid] = g_tok[e * MAXP + r];
    }
    __syncthreads();

    const int tx = tid & 15;
    const int ty = tid >> 4;
    const int arow = tid >> 2;              // 0..63
    const int akk  = (tid & 3) * 4;         // 0,4,8,12
    const int brow = tid >> 4;              // 0..15
    const int bcol = (tid & 15) * 4;        // 0..60

    const float* Bbase = wfc + (size_t)e * H_DIM * I_DIM;

    float acc[4][4];
#pragma unroll
    for (int i = 0; i < 4; i++)
#pragma unroll
        for (int j = 0; j < 4; j++) acc[i][j] = 0.f;

    for (int k0 = 0; k0 < H_DIM; k0 += 16) {
        float4 av = *(const float4*)(x + (size_t)stok[arow] * H_DIM + k0 + akk);
        As[akk + 0][arow] = av.x;
        As[akk + 1][arow] = av.y;
        As[akk + 2][arow] = av.z;
        As[akk + 3][arow] = av.w;
        float4 bv = *(const float4*)(Bbase + (size_t)(k0 + brow) * I_DIM + col0 + bcol);
        *(float4*)&Bs[brow][bcol] = bv;
        __syncthreads();
#pragma unroll
        for (int k = 0; k < 16; k++) {
            float4 a = *(const float4*)&As[k][ty * 4];
            float4 b = *(const float4*)&Bs[k][tx * 4];
            float ar[4] = {a.x, a.y, a.z, a.w};
            float br[4] = {b.x, b.y, b.z, b.w};
#pragma unroll
            for (int i = 0; i < 4; i++)
#pragma unroll
                for (int j = 0; j < 4; j++)
                    acc[i][j] += ar[i] * br[j];
        }
        __syncthreads();
    }

#pragma unroll
    for (int i = 0; i < 4; i++) {
        int lr = row0 + ty * 4 + i;
        if (lr < cnt) {
            float* dst = g_h + (size_t)(off + lr) * I_DIM + col0 + tx * 4;
            float4 v;
            v.x = gelu_exact(acc[i][0]);
            v.y = gelu_exact(acc[i][1]);
            v.z = gelu_exact(acc[i][2]);
            v.w = gelu_exact(acc[i][3]);
            *(float4*)dst = v;
        }
    }
}

// ============================================================
// PROJ: out[tok(r), :] += gate(r) * ( h[off+r, :] @ Wproj[e] )
// Same tiling; scatter via atomicAdd.
// grid = (H/64, MAXP/64, E)
// ============================================================
__global__ __launch_bounds__(256)
void proj_kernel(const float* __restrict__ wproj,
                 float* __restrict__ out) {
    const int e    = blockIdx.z;
    const int cnt  = g_count[e];
    const int row0 = blockIdx.y * 64;
    if (row0 >= cnt) return;
    const int col0 = blockIdx.x * 64;
    const int off  = g_offset[e];

    __shared__ float As[16][64];
    __shared__ float Bs[16][64];

    const int tid = threadIdx.x;
    const int tx = tid & 15;
    const int ty = tid >> 4;
    const int arow = tid >> 2;
    const int akk  = (tid & 3) * 4;
    const int brow = tid >> 4;
    const int bcol = (tid & 15) * 4;

    int ar_clamped = row0 + arow;
    if (ar_clamped >= cnt) ar_clamped = cnt - 1;
    const float* Arow = g_h + (size_t)(off + ar_clamped) * I_DIM;
    const float* Bbase = wproj + (size_t)e * I_DIM * H_DIM;

    float acc[4][4];
#pragma unroll
    for (int i = 0; i < 4; i++)
#pragma unroll
        for (int j = 0; j < 4; j++) acc[i][j] = 0.f;

    for (int k0 = 0; k0 < I_DIM; k0 += 16) {
        float4 av = *(const float4*)(Arow + k0 + akk);
        As[akk + 0][arow] = av.x;
        As[akk + 1][arow] = av.y;
        As[akk + 2][arow] = av.z;
        As[akk + 3][arow] = av.w;
        float4 bv = *(const float4*)(Bbase + (size_t)(k0 + brow) * H_DIM + col0 + bcol);
        *(float4*)&Bs[brow][bcol] = bv;
        __syncthreads();
#pragma unroll
        for (int k = 0; k < 16; k++) {
            float4 a = *(const float4*)&As[k][ty * 4];
            float4 b = *(const float4*)&Bs[k][tx * 4];
            float ar[4] = {a.x, a.y, a.z, a.w};
            float br[4] = {b.x, b.y, b.z, b.w};
#pragma unroll
            for (int i = 0; i < 4; i++)
#pragma unroll
                for (int j = 0; j < 4; j++)
                    acc[i][j] += ar[i] * br[j];
        }
        __syncthreads();
    }

#pragma unroll
    for (int i = 0; i < 4; i++) {
        int lr = row0 + ty * 4 + i;
        if (lr < cnt) {
            int   tok  = g_tok [e * MAXP + lr];
            float gate = g_gate[e * MAXP + lr];
            float* dst = out + (size_t)tok * H_DIM + col0 + tx * 4;
#pragma unroll
            for (int j = 0; j < 4; j++)
                atomicAdd(dst + j, gate * acc[i][j]);
        }
    }
}

// ============================================================
extern "C" void kernel_launch(void* const* d_in, const int* in_sizes, int n_in,
                              void* d_out, int out_size) {
    const float* x     = (const float*)d_in[0];   // [T, H]
    const float* rw    = (const float*)d_in[1];   // [T, K]
    const int*   sel   = (const int*)  d_in[2];   // [T, K]
    const float* wfc   = (const float*)d_in[3];   // [E, H, I]
    const float* wproj = (const float*)d_in[4];   // [E, I, H]
    float* out = (float*)d_out;                   // [T, H]

    cudaMemsetAsync(out, 0, (size_t)T_TOK * H_DIM * sizeof(float));

    route_kernel<<<1, 256>>>(rw, sel);

    dim3 fc_grid(I_DIM / 64, MAXP / 64, E_NUM);
    fc_kernel<<<fc_grid, 256>>>(x, wfc);

    dim3 pj_grid(H_DIM / 64, MAXP / 64, E_NUM);
    proj_kernel<<<pj_grid, 256>>>(wproj, out);
}

// round 2
// speedup vs baseline: 2.2160x; 2.2160x over previous
#include <cuda_runtime.h>
#include <math.h>

#define T_TOK 4096
#define H_DIM 1024
#define I_DIM 2048
#define E_NUM 8
#define K_TOP 2
#define MAXP (T_TOK * K_TOP)

#define BM 128
#define BN 128
#define BK 16
#define AP 20    // A smem row stride (floats), conflict-free frag loads
#define BP 136   // B smem row stride (floats), conflict-free frag loads

// ---- static device scratch ----
__device__ int   g_count[E_NUM];
__device__ int   g_offset[E_NUM];
__device__ int   g_tok [E_NUM * MAXP];
__device__ float g_gate[E_NUM * MAXP];
__device__ float g_h[(size_t)MAXP * I_DIM];   // 64MB intermediate

// ============================================================
// Routing
// ============================================================
__global__ void route_kernel(const float* __restrict__ rw,
                             const int*   __restrict__ sel) {
    __shared__ int sc[E_NUM];
    int tid = threadIdx.x;
    if (tid < E_NUM) sc[tid] = 0;
    __syncthreads();
    for (int p = tid; p < T_TOK * K_TOP; p += blockDim.x) {
        int e = sel[p];
        int slot = atomicAdd(&sc[e], 1);
        g_tok [e * MAXP + slot] = p / K_TOP;
        g_gate[e * MAXP + slot] = rw[p];
    }
    __syncthreads();
    if (tid == 0) {
        int off = 0;
        for (int e = 0; e < E_NUM; e++) {
            g_count[e]  = sc[e];
            g_offset[e] = off;
            off += sc[e];
        }
    }
}

__device__ __forceinline__ float gelu_exact(float v) {
    return 0.5f * v * (1.0f + erff(v * 0.7071067811865476f));
}

__device__ __forceinline__ unsigned f2tf(float f) {
    unsigned u;
    asm("cvt.rna.tf32.f32 %0, %1;" : "=r"(u) : "f"(f));
    return u;
}

__device__ __forceinline__ void mma_tf32(float* d, const unsigned* a, const unsigned* b) {
    asm volatile(
        "mma.sync.aligned.m16n8k8.row.col.f32.tf32.tf32.f32 "
        "{%0,%1,%2,%3},{%4,%5,%6,%7},{%8,%9},{%0,%1,%2,%3};"
        : "+f"(d[0]), "+f"(d[1]), "+f"(d[2]), "+f"(d[3])
        : "r"(a[0]), "r"(a[1]), "r"(a[2]), "r"(a[3]),
          "r"(b[0]), "r"(b[1]));
}

// store 8 floats (2 float4) tf32-converted into smem row
__device__ __forceinline__ void sts_tf32_8(float* dst, float4 v0, float4 v1) {
    float4 o0, o1;
    o0.x = __uint_as_float(f2tf(v0.x)); o0.y = __uint_as_float(f2tf(v0.y));
    o0.z = __uint_as_float(f2tf(v0.z)); o0.w = __uint_as_float(f2tf(v0.w));
    o1.x = __uint_as_float(f2tf(v1.x)); o1.y = __uint_as_float(f2tf(v1.y));
    o1.z = __uint_as_float(f2tf(v1.z)); o1.w = __uint_as_float(f2tf(v1.w));
    *(float4*)(dst)     = o0;
    *(float4*)(dst + 4) = o1;
}

// ============================================================
// FC: h[off+r, :] = gelu( x[tok(r), :] @ Wfc[e] )   (TF32 MMA)
// ============================================================
__global__ __launch_bounds__(256, 1)
void fc_mma(const float* __restrict__ x,
            const float* __restrict__ wfc) {
    const int e    = blockIdx.z;
    const int cnt  = g_count[e];
    const int row0 = blockIdx.y * BM;
    if (row0 >= cnt) return;
    const int col0 = blockIdx.x * BN;
    const int off  = g_offset[e];

    __shared__ float As[2][BM][AP];
    __shared__ float Bs[2][BK][BP];
    __shared__ int   stok[BM];

    const int tid = threadIdx.x;
    if (tid < BM) {
        int r = row0 + tid;
        if (r >= cnt) r = cnt - 1;
        stok[tid] = g_tok[e * MAXP + r];
    }
    __syncthreads();

    // global load mapping (fixed per thread)
    const int arow = tid >> 1;
    const int acol = (tid & 1) * 8;
    const float* aptr = x + (size_t)stok[arow] * H_DIM + acol;
    const int brow = tid >> 4;
    const int bcol = (tid & 15) * 8;
    const float* bptr = wfc + (size_t)e * H_DIM * I_DIM + (size_t)brow * I_DIM + col0 + bcol;

    const int warp = tid >> 5;
    const int lane = tid & 31;
    const int wm = warp >> 2;        // 0..1 -> 64-row warp tile
    const int wn = warp & 3;         // 0..3 -> 32-col warp tile
    const int g  = lane >> 2;
    const int t  = lane & 3;

    float acc[4][4][4];
#pragma unroll
    for (int mt = 0; mt < 4; mt++)
#pragma unroll
        for (int nt = 0; nt < 4; nt++)
#pragma unroll
            for (int r = 0; r < 4; r++) acc[mt][nt][r] = 0.f;

    const int NK = H_DIM / BK;

    float4 pa0 = *(const float4*)(aptr);
    float4 pa1 = *(const float4*)(aptr + 4);
    float4 pb0 = *(const float4*)(bptr);
    float4 pb1 = *(const float4*)(bptr + 4);

    sts_tf32_8(&As[0][arow][acol], pa0, pa1);
    sts_tf32_8(&Bs[0][brow][bcol], pb0, pb1);
    __syncthreads();

    for (int it = 0; it < NK; ++it) {
        const int cur = it & 1;
        if (it + 1 < NK) {
            pa0 = *(const float4*)(aptr + (it + 1) * BK);
            pa1 = *(const float4*)(aptr + (it + 1) * BK + 4);
            pb0 = *(const float4*)(bptr + (size_t)(it + 1) * BK * I_DIM);
            pb1 = *(const float4*)(bptr + (size_t)(it + 1) * BK * I_DIM + 4);
        }
#pragma unroll
        for (int ks = 0; ks < 2; ks++) {
            const int kc = ks * 8 + t;
            unsigned afr[4][4], bfr[4][2];
#pragma unroll
            for (int mt = 0; mt < 4; mt++) {
                const int r = wm * 64 + mt * 16;
                afr[mt][0] = __float_as_uint(As[cur][r + g][kc]);
                afr[mt][1] = __float_as_uint(As[cur][r + g + 8][kc]);
                afr[mt][2] = __float_as_uint(As[cur][r + g][kc + 4]);
                afr[mt][3] = __float_as_uint(As[cur][r + g + 8][kc + 4]);
            }
#pragma unroll
            for (int nt = 0; nt < 4; nt++) {
                const int c = wn * 32 + nt * 8 + g;
                bfr[nt][0] = __float_as_uint(Bs[cur][kc][c]);
                bfr[nt][1] = __float_as_uint(Bs[cur][kc + 4][c]);
            }
#pragma unroll
            for (int mt = 0; mt < 4; mt++)
#pragma unroll
                for (int nt = 0; nt < 4; nt++)
                    mma_tf32(acc[mt][nt], afr[mt], bfr[nt]);
        }
        if (it + 1 < NK) {
            sts_tf32_8(&As[cur ^ 1][arow][acol], pa0, pa1);
            sts_tf32_8(&Bs[cur ^ 1][brow][bcol], pb0, pb1);
        }
        __syncthreads();
    }

    // epilogue: gelu + store to g_h
#pragma unroll
    for (int mt = 0; mt < 4; mt++) {
        const int lr0 = row0 + wm * 64 + mt * 16 + g;
        const int lr1 = lr0 + 8;
#pragma unroll
        for (int nt = 0; nt < 4; nt++) {
            const int c = col0 + wn * 32 + nt * 8 + 2 * t;
            if (lr0 < cnt) {
                float2 v;
                v.x = gelu_exact(acc[mt][nt][0]);
                v.y = gelu_exact(acc[mt][nt][1]);
                *(float2*)(g_h + (size_t)(off + lr0) * I_DIM + c) = v;
            }
            if (lr1 < cnt) {
                float2 v;
                v.x = gelu_exact(acc[mt][nt][2]);
                v.y = gelu_exact(acc[mt][nt][3]);
                *(float2*)(g_h + (size_t)(off + lr1) * I_DIM + c) = v;
            }
        }
    }
}

// ============================================================
// PROJ: out[tok(r), :] += gate(r) * ( h[off+r, :] @ Wproj[e] )
// ============================================================
__global__ __launch_bounds__(256, 1)
void proj_mma(const float* __restrict__ wproj,
              float* __restrict__ out) {
    const int e    = blockIdx.z;
    const int cnt  = g_count[e];
    const int row0 = blockIdx.y * BM;
    if (row0 >= cnt) return;
    const int col0 = blockIdx.x * BN;
    const int off  = g_offset[e];

    __shared__ float As[2][BM][AP];
    __shared__ float Bs[2][BK][BP];
    __shared__ int   stok[BM];
    __shared__ float sgate[BM];

    const int tid = threadIdx.x;
    if (tid < BM) {
        int r = row0 + tid;
        if (r >= cnt) r = cnt - 1;
        stok[tid]  = g_tok [e * MAXP + r];
        sgate[tid] = g_gate[e * MAXP + r];
    }
    __syncthreads();

    const int arow = tid >> 1;
    const int acol = (tid & 1) * 8;
    int ar = row0 + arow;
    if (ar >= cnt) ar = cnt - 1;
    const float* aptr = g_h + (size_t)(off + ar) * I_DIM + acol;
    const int brow = tid >> 4;
    const int bcol = (tid & 15) * 8;
    const float* bptr = wproj + (size_t)e * I_DIM * H_DIM + (size_t)brow * H_DIM + col0 + bcol;

    const int warp = tid >> 5;
    const int lane = tid & 31;
    const int wm = warp >> 2;
    const int wn = warp & 3;
    const int g  = lane >> 2;
    const int t  = lane & 3;

    float acc[4][4][4];
#pragma unroll
    for (int mt = 0; mt < 4; mt++)
#pragma unroll
        for (int nt = 0; nt < 4; nt++)
#pragma unroll
            for (int r = 0; r < 4; r++) acc[mt][nt][r] = 0.f;

    const int NK = I_DIM / BK;

    float4 pa0 = *(const float4*)(aptr);
    float4 pa1 = *(const float4*)(aptr + 4);
    float4 pb0 = *(const float4*)(bptr);
    float4 pb1 = *(const float4*)(bptr + 4);

    sts_tf32_8(&As[0][arow][acol], pa0, pa1);
    sts_tf32_8(&Bs[0][brow][bcol], pb0, pb1);
    __syncthreads();

    for (int it = 0; it < NK; ++it) {
        const int cur = it & 1;
        if (it + 1 < NK) {
            pa0 = *(const float4*)(aptr + (it + 1) * BK);
            pa1 = *(const float4*)(aptr + (it + 1) * BK + 4);
            pb0 = *(const float4*)(bptr + (size_t)(it + 1) * BK * H_DIM);
            pb1 = *(const float4*)(bptr + (size_t)(it + 1) * BK * H_DIM + 4);
        }
#pragma unroll
        for (int ks = 0; ks < 2; ks++) {
            const int kc = ks * 8 + t;
            unsigned afr[4][4], bfr[4][2];
#pragma unroll
            for (int mt = 0; mt < 4; mt++) {
                const int r = wm * 64 + mt * 16;
                afr[mt][0] = __float_as_uint(As[cur][r + g][kc]);
                afr[mt][1] = __float_as_uint(As[cur][r + g + 8][kc]);
                afr[mt][2] = __float_as_uint(As[cur][r + g][kc + 4]);
                afr[mt][3] = __float_as_uint(As[cur][r + g + 8][kc + 4]);
            }
#pragma unroll
            for (int nt = 0; nt < 4; nt++) {
                const int c = wn * 32 + nt * 8 + g;
                bfr[nt][0] = __float_as_uint(Bs[cur][kc][c]);
                bfr[nt][1] = __float_as_uint(Bs[cur][kc + 4][c]);
            }
#pragma unroll
            for (int mt = 0; mt < 4; mt++)
#pragma unroll
                for (int nt = 0; nt < 4; nt++)
                    mma_tf32(acc[mt][nt], afr[mt], bfr[nt]);
        }
        if (it + 1 < NK) {
            sts_tf32_8(&As[cur ^ 1][arow][acol], pa0, pa1);
            sts_tf32_8(&Bs[cur ^ 1][brow][bcol], pb0, pb1);
        }
        __syncthreads();
    }

    // epilogue: gated scatter via atomicAdd
#pragma unroll
    for (int mt = 0; mt < 4; mt++) {
        const int l0 = wm * 64 + mt * 16 + g;
        const int l1 = l0 + 8;
        const int lr0 = row0 + l0;
        const int lr1 = row0 + l1;
#pragma unroll
        for (int nt = 0; nt < 4; nt++) {
            const int c = col0 + wn * 32 + nt * 8 + 2 * t;
            if (lr0 < cnt) {
                const float gate = sgate[l0];
                float* dst = out + (size_t)stok[l0] * H_DIM + c;
                atomicAdd(dst,     gate * acc[mt][nt][0]);
                atomicAdd(dst + 1, gate * acc[mt][nt][1]);
            }
            if (lr1 < cnt) {
                const float gate = sgate[l1];
                float* dst = out + (size_t)stok[l1] * H_DIM + c;
                atomicAdd(dst,     gate * acc[mt][nt][2]);
                atomicAdd(dst + 1, gate * acc[mt][nt][3]);
            }
        }
    }
}

// ============================================================
extern "C" void kernel_launch(void* const* d_in, const int* in_sizes, int n_in,
                              void* d_out, int out_size) {
    const float* x     = (const float*)d_in[0];
    const float* rw    = (const float*)d_in[1];
    const int*   sel   = (const int*)  d_in[2];
    const float* wfc   = (const float*)d_in[3];
    const float* wproj = (const float*)d_in[4];
    float* out = (float*)d_out;

    cudaMemsetAsync(out, 0, (size_t)T_TOK * H_DIM * sizeof(float));

    route_kernel<<<1, 512>>>(rw, sel);

    dim3 fc_grid(I_DIM / BN, MAXP / BM, E_NUM);
    fc_mma<<<fc_grid, 256>>>(x, wfc);

    dim3 pj_grid(H_DIM / BN, MAXP / BM, E_NUM);
    proj_mma<<<pj_grid, 256>>>(wproj, out);
}

// round 4
// speedup vs baseline: 2.7666x; 1.2485x over previous
#include <cuda_runtime.h>
#include <math.h>
#include <stdint.h>

#define T_TOK 4096
#define H_DIM 1024
#define I_DIM 2048
#define E_NUM 8
#define K_TOP 2
#define MAXP (T_TOK * K_TOP)

#define BM 128
#define BN 128
#define BK 16
#define AP 20                 /* A smem row stride (floats): conflict-free frag LDS */
#define BP 136                /* B smem row stride (floats): conflict-free frag LDS */
#define AWORDS (BM * AP)      /* 2560 */
#define BWORDS (BK * BP)      /* 2176 */
#define STGW   (AWORDS + BWORDS)
#define NST 3
#define SMEM_SZ (NST * STGW * 4)

// ---- static device scratch ----
__device__ int   g_count[E_NUM];
__device__ int   g_offset[E_NUM];
__device__ int   g_tok [E_NUM * MAXP];
__device__ float g_gate[E_NUM * MAXP];
__device__ float g_xg[(size_t)MAXP * H_DIM];              // gathered activations (tf32-rounded)
__device__ float g_h [(size_t)MAXP * I_DIM];              // gelu(fc) intermediate (tf32-rounded)
__device__ float g_wfc_r  [(size_t)E_NUM * H_DIM * I_DIM]; // tf32-rounded wfc
__device__ float g_wproj_r[(size_t)E_NUM * I_DIM * H_DIM]; // tf32-rounded wproj

// ================= helpers =================
__device__ __forceinline__ uint32_t smem_u32(const void* p) {
    uint32_t a;
    asm("{ .reg .u64 t; cvta.to.shared.u64 t, %1; cvt.u32.u64 %0, t; }" : "=r"(a) : "l"(p));
    return a;
}
__device__ __forceinline__ unsigned f2tf(float f) {
    unsigned u;
    asm("cvt.rna.tf32.f32 %0, %1;" : "=r"(u) : "f"(f));
    return u;
}
__device__ __forceinline__ float gelu_exact(float v) {
    return 0.5f * v * (1.0f + erff(v * 0.7071067811865476f));
}
__device__ __forceinline__ void cp16(uint32_t dst, const void* src) {
    asm volatile("cp.async.ca.shared.global [%0], [%1], 16;" :: "r"(dst), "l"(src) : "memory");
}
__device__ __forceinline__ void cp_commit() {
    asm volatile("cp.async.commit_group;" ::: "memory");
}
__device__ __forceinline__ void cp_wait1() {
    asm volatile("cp.async.wait_group 1;" ::: "memory");
}
__device__ __forceinline__ void mma_tf32(float* d, const unsigned* a, const unsigned* b) {
    asm volatile(
        "mma.sync.aligned.m16n8k8.row.col.f32.tf32.tf32.f32 "
        "{%0,%1,%2,%3},{%4,%5,%6,%7},{%8,%9},{%0,%1,%2,%3};"
        : "+f"(d[0]), "+f"(d[1]), "+f"(d[2]), "+f"(d[3])
        : "r"(a[0]), "r"(a[1]), "r"(a[2]), "r"(a[3]),
          "r"(b[0]), "r"(b[1]));
}

// ================= routing =================
__global__ void route_kernel(const float* __restrict__ rw,
                             const int*   __restrict__ sel) {
    __shared__ int sc[E_NUM];
    int tid = threadIdx.x;
    if (tid < E_NUM) sc[tid] = 0;
    __syncthreads();
    for (int p = tid; p < T_TOK * K_TOP; p += blockDim.x) {
        int e = sel[p];
        int slot = atomicAdd(&sc[e], 1);
        g_tok [e * MAXP + slot] = p / K_TOP;
        g_gate[e * MAXP + slot] = rw[p];
    }
    __syncthreads();
    if (tid == 0) {
        int off = 0;
        for (int e = 0; e < E_NUM; e++) {
            g_count[e]  = sc[e];
            g_offset[e] = off;
            off += sc[e];
        }
    }
}

// ================= gather activations (tf32-rounded) =================
__global__ void gather_kernel(const float* __restrict__ x) {
    int r = blockIdx.x;
    int e = 0;
#pragma unroll
    for (int i = 0; i < E_NUM; i++)
        if (r >= g_offset[i] + g_count[i]) e = i + 1;
    int tok = g_tok[e * MAXP + (r - g_offset[e])];
    const float4* src = (const float4*)(x + (size_t)tok * H_DIM);
    float4* dst = (float4*)(g_xg + (size_t)r * H_DIM);
    float4 v = src[threadIdx.x];
    v.x = __uint_as_float(f2tf(v.x)); v.y = __uint_as_float(f2tf(v.y));
    v.z = __uint_as_float(f2tf(v.z)); v.w = __uint_as_float(f2tf(v.w));
    dst[threadIdx.x] = v;
}

// ================= weight round-copy (tf32) =================
__global__ void roundcpy_kernel(const float* __restrict__ src,
                                float* __restrict__ dst, int n4) {
    int i = blockIdx.x * blockDim.x + threadIdx.x;
    int stride = gridDim.x * blockDim.x;
    for (; i < n4; i += stride) {
        float4 v = ((const float4*)src)[i];
        v.x = __uint_as_float(f2tf(v.x)); v.y = __uint_as_float(f2tf(v.y));
        v.z = __uint_as_float(f2tf(v.z)); v.w = __uint_as_float(f2tf(v.w));
        ((float4*)dst)[i] = v;
    }
}

// ================= grouped GEMM (tf32 mma.sync, cp.async 3-stage) ======
// IS_FC:  g_h[off+r,:] = gelu( g_xg[off+r,:] @ wfc[e] )
// !IS_FC: out[tok,:]  += gate * ( g_h[off+r,:] @ wproj[e] )
template <bool IS_FC>
__global__ __launch_bounds__(256, 2)
void moe_gemm(const float* __restrict__ wsrc, float* __restrict__ out) {
    const int e    = blockIdx.z;
    const int cnt  = g_count[e];
    const int row0 = blockIdx.y * BM;
    if (row0 >= cnt) return;
    const int col0 = blockIdx.x * BN;
    const int off  = g_offset[e];
    const int KDIM = IS_FC ? H_DIM : I_DIM;
    const int NDIM = IS_FC ? I_DIM : H_DIM;
    const int NKB  = KDIM / BK;

    extern __shared__ float sm[];
    const uint32_t smb = smem_u32(sm);

    const int tid  = threadIdx.x;
    const int warp = tid >> 5;
    const int lane = tid & 31;

    // ---- staging maps ----
    const int arow = tid >> 1;              // 0..127
    const int acol = (tid & 1) * 8;         // 0 or 8
    int ga = row0 + arow; if (ga >= cnt) ga = cnt - 1;
    const float* aSrc = (IS_FC ? g_xg : g_h) + (size_t)(off + ga) * KDIM + acol;
    const int brow = tid >> 4;              // 0..15
    const int bcol = (tid & 15) * 8;        // 0..120
    const float* bSrc = wsrc + (size_t)e * H_DIM * I_DIM
                      + (size_t)brow * NDIM + col0 + bcol;

    uint32_t aDst[NST], bDst[NST];
#pragma unroll
    for (int s = 0; s < NST; s++) {
        aDst[s] = smb + (s * STGW + arow * AP + acol) * 4;
        bDst[s] = smb + (s * STGW + AWORDS + brow * BP + bcol) * 4;
    }

#define ISSUE(kb_, st_) do { \
    const float* as_ = aSrc + (kb_) * BK; \
    cp16(aDst[st_], as_); cp16(aDst[st_] + 16, as_ + 4); \
    const float* bs_ = bSrc + (size_t)(kb_) * BK * NDIM; \
    cp16(bDst[st_], bs_); cp16(bDst[st_] + 16, bs_ + 4); \
    } while (0)

    // ---- compute maps ----
    const int wm = warp >> 2;        // 0..1 : 64-row warp tile
    const int wn = warp & 3;         // 0..3 : 32-col warp tile
    const int g  = lane >> 2;
    const int t  = lane & 3;

    float acc[4][4][4];
#pragma unroll
    for (int mt = 0; mt < 4; mt++)
#pragma unroll
        for (int nt = 0; nt < 4; nt++)
#pragma unroll
            for (int r = 0; r < 4; r++) acc[mt][nt][r] = 0.f;

    // prologue: 2 stages in flight
    ISSUE(0, 0); cp_commit();
    ISSUE(1, 1); cp_commit();

#pragma unroll 1
    for (int kb = 0; kb < NKB; kb++) {
        cp_wait1();
        __syncthreads();
        const int st = kb % NST;
        if (kb + 2 < NKB) ISSUE(kb + 2, (kb + 2) % NST);
        cp_commit();

        const float* As = sm + st * STGW;
        const float* Bs = sm + st * STGW + AWORDS;
#pragma unroll
        for (int ks = 0; ks < 2; ks++) {
            const int kc = ks * 8 + t;
            unsigned afr[4][4], bfr[4][2];
#pragma unroll
            for (int mt = 0; mt < 4; mt++) {
                const int r = wm * 64 + mt * 16;
                afr[mt][0] = __float_as_uint(As[(r + g) * AP + kc]);
                afr[mt][1] = __float_as_uint(As[(r + g + 8) * AP + kc]);
                afr[mt][2] = __float_as_uint(As[(r + g) * AP + kc + 4]);
                afr[mt][3] = __float_as_uint(As[(r + g + 8) * AP + kc + 4]);
            }
#pragma unroll
            for (int nt = 0; nt < 4; nt++) {
                const int c = wn * 32 + nt * 8 + g;
                bfr[nt][0] = __float_as_uint(Bs[kc * BP + c]);
                bfr[nt][1] = __float_as_uint(Bs[(kc + 4) * BP + c]);
            }
#pragma unroll
            for (int mt = 0; mt < 4; mt++)
#pragma unroll
                for (int nt = 0; nt < 4; nt++)
                    mma_tf32(acc[mt][nt], afr[mt], bfr[nt]);
        }
    }
#undef ISSUE

    // ---- epilogue ----
#pragma unroll
    for (int mt = 0; mt < 4; mt++) {
        const int l0 = wm * 64 + mt * 16 + g;
        const int l1 = l0 + 8;
        const int lr0 = row0 + l0;
        const int lr1 = row0 + l1;
#pragma unroll
        for (int nt = 0; nt < 4; nt++) {
            const int c = col0 + wn * 32 + nt * 8 + 2 * t;
            if (IS_FC) {
                if (lr0 < cnt) {
                    float2 v;
                    v.x = __uint_as_float(f2tf(gelu_exact(acc[mt][nt][0])));
                    v.y = __uint_as_float(f2tf(gelu_exact(acc[mt][nt][1])));
                    *(float2*)(g_h + (size_t)(off + lr0) * I_DIM + c) = v;
                }
                if (lr1 < cnt) {
                    float2 v;
                    v.x = __uint_as_float(f2tf(gelu_exact(acc[mt][nt][2])));
                    v.y = __uint_as_float(f2tf(gelu_exact(acc[mt][nt][3])));
                    *(float2*)(g_h + (size_t)(off + lr1) * I_DIM + c) = v;
                }
            } else {
                if (lr0 < cnt) {
                    const float gate = g_gate[e * MAXP + lr0];
                    float* dst = out + (size_t)g_tok[e * MAXP + lr0] * H_DIM + c;
                    atomicAdd(dst,     gate * acc[mt][nt][0]);
                    atomicAdd(dst + 1, gate * acc[mt][nt][1]);
                }
                if (lr1 < cnt) {
                    const float gate = g_gate[e * MAXP + lr1];
                    float* dst = out + (size_t)g_tok[e * MAXP + lr1] * H_DIM + c;
                    atomicAdd(dst,     gate * acc[mt][nt][2]);
                    atomicAdd(dst + 1, gate * acc[mt][nt][3]);
                }
            }
        }
    }
}

// ================= launch =================
extern "C" void kernel_launch(void* const* d_in, const int* in_sizes, int n_in,
                              void* d_out, int out_size) {
    const float* x     = (const float*)d_in[0];
    const float* rw    = (const float*)d_in[1];
    const int*   sel   = (const int*)  d_in[2];
    const float* wfc   = (const float*)d_in[3];
    const float* wproj = (const float*)d_in[4];
    float* out = (float*)d_out;

    static int attr_set = 0;
    cudaFuncSetAttribute(moe_gemm<true>,  cudaFuncAttributeMaxDynamicSharedMemorySize, SMEM_SZ);
    cudaFuncSetAttribute(moe_gemm<false>, cudaFuncAttributeMaxDynamicSharedMemorySize, SMEM_SZ);
    (void)attr_set;

    float* wfcR;  cudaGetSymbolAddress((void**)&wfcR,  g_wfc_r);
    float* wprR;  cudaGetSymbolAddress((void**)&wprR,  g_wproj_r);

    cudaMemsetAsync(out, 0, (size_t)T_TOK * H_DIM * sizeof(float));
    route_kernel<<<1, 512>>>(rw, sel);
    gather_kernel<<<MAXP, 256>>>(x);
    roundcpy_kernel<<<2048, 256>>>(wfc,   wfcR, E_NUM * H_DIM * I_DIM / 4);
    roundcpy_kernel<<<2048, 256>>>(wproj, wprR, E_NUM * I_DIM * H_DIM / 4);

    dim3 fc_grid(I_DIM / BN, MAXP / BM, E_NUM);
    moe_gemm<true><<<fc_grid, 256, SMEM_SZ>>>(wfcR, out);

    dim3 pj_grid(H_DIM / BN, MAXP / BM, E_NUM);
    moe_gemm<false><<<pj_grid, 256, SMEM_SZ>>>(wprR, out);
}

// round 5
// speedup vs baseline: 5.6945x; 2.0583x over previous
#include <cuda_runtime.h>
#include <cuda_fp16.h>
#include <math.h>
#include <stdint.h>

#define T_TOK 4096
#define H_DIM 1024
#define I_DIM 2048
#define E_NUM 8
#define K_TOP 2
#define MAXP (T_TOK * K_TOP)

#define BM 128
#define BN 128
#define BK 32                      /* halves per k-stage */
#define AROW_B 80                  /* A smem row stride bytes (64 data + 16 pad) */
#define BROW_B 272                 /* B smem row stride bytes (256 data + 16 pad) */
#define ABYTES (BM * AROW_B)       /* 10240 */
#define BBYTES (BK * BROW_B)       /* 8704  */
#define STG    (ABYTES + BBYTES)   /* 18944 */
#define NST 3
#define SMEM_SZ (NST * STG)        /* 56832 */

// ---- static device scratch ----
__device__ int    g_count[E_NUM];
__device__ int    g_offset[E_NUM];
__device__ int    g_tok [E_NUM * MAXP];
__device__ float  g_gate[E_NUM * MAXP];
__device__ __half g_xg[(size_t)MAXP * H_DIM];               // gathered activations fp16
__device__ __half g_h [(size_t)MAXP * I_DIM];               // gelu(fc) intermediate fp16
__device__ __half g_wfc_h  [(size_t)E_NUM * H_DIM * I_DIM]; // fp16 wfc
__device__ __half g_wproj_h[(size_t)E_NUM * I_DIM * H_DIM]; // fp16 wproj

// ================= helpers =================
__device__ __forceinline__ uint32_t smem_u32(const void* p) {
    uint32_t a;
    asm("{ .reg .u64 t; cvta.to.shared.u64 t, %1; cvt.u32.u64 %0, t; }" : "=r"(a) : "l"(p));
    return a;
}
__device__ __forceinline__ float gelu_exact(float v) {
    return 0.5f * v * (1.0f + erff(v * 0.7071067811865476f));
}
__device__ __forceinline__ void cp16(uint32_t dst, const void* src) {
    asm volatile("cp.async.ca.shared.global [%0], [%1], 16;" :: "r"(dst), "l"(src) : "memory");
}
__device__ __forceinline__ void cp_commit() {
    asm volatile("cp.async.commit_group;" ::: "memory");
}
__device__ __forceinline__ void cp_wait1() {
    asm volatile("cp.async.wait_group 1;" ::: "memory");
}
__device__ __forceinline__ void ldsm_x4(unsigned* r, uint32_t addr) {
    asm volatile("ldmatrix.sync.aligned.m8n8.x4.shared.b16 {%0,%1,%2,%3}, [%4];"
                 : "=r"(r[0]), "=r"(r[1]), "=r"(r[2]), "=r"(r[3]) : "r"(addr));
}
__device__ __forceinline__ void ldsm_x4_t(unsigned* r, uint32_t addr) {
    asm volatile("ldmatrix.sync.aligned.m8n8.x4.trans.shared.b16 {%0,%1,%2,%3}, [%4];"
                 : "=r"(r[0]), "=r"(r[1]), "=r"(r[2]), "=r"(r[3]) : "r"(addr));
}
__device__ __forceinline__ void mma_f16(float* d, const unsigned* a, const unsigned* b) {
    asm volatile(
        "mma.sync.aligned.m16n8k16.row.col.f32.f16.f16.f32 "
        "{%0,%1,%2,%3},{%4,%5,%6,%7},{%8,%9},{%0,%1,%2,%3};"
        : "+f"(d[0]), "+f"(d[1]), "+f"(d[2]), "+f"(d[3])
        : "r"(a[0]), "r"(a[1]), "r"(a[2]), "r"(a[3]),
          "r"(b[0]), "r"(b[1]));
}

// ================= routing =================
__global__ void route_kernel(const float* __restrict__ rw,
                             const int*   __restrict__ sel) {
    __shared__ int sc[E_NUM];
    int tid = threadIdx.x;
    if (tid < E_NUM) sc[tid] = 0;
    __syncthreads();
    for (int p = tid; p < T_TOK * K_TOP; p += blockDim.x) {
        int e = sel[p];
        int slot = atomicAdd(&sc[e], 1);
        g_tok [e * MAXP + slot] = p / K_TOP;
        g_gate[e * MAXP + slot] = rw[p];
    }
    __syncthreads();
    if (tid == 0) {
        int off = 0;
        for (int e = 0; e < E_NUM; e++) {
            g_count[e]  = sc[e];
            g_offset[e] = off;
            off += sc[e];
        }
    }
}

// ================= gather activations -> fp16 =================
__global__ void gather_kernel(const float* __restrict__ x) {
    int r = blockIdx.x;
    int e = 0;
#pragma unroll
    for (int i = 0; i < E_NUM; i++)
        if (r >= g_offset[i] + g_count[i]) e = i + 1;
    int tok = g_tok[e * MAXP + (r - g_offset[e])];
    const float4* src = (const float4*)(x + (size_t)tok * H_DIM);
    float4 v = src[threadIdx.x];
    __half2 h0 = __floats2half2_rn(v.x, v.y);
    __half2 h1 = __floats2half2_rn(v.z, v.w);
    uint2 pk = make_uint2(*(uint32_t*)&h0, *(uint32_t*)&h1);
    ((uint2*)(g_xg + (size_t)r * H_DIM))[threadIdx.x] = pk;
}

// ================= weight convert -> fp16 =================
__global__ void convert_kernel(const float* __restrict__ src,
                               __half* __restrict__ dst, int n4) {
    int i = blockIdx.x * blockDim.x + threadIdx.x;
    int stride = gridDim.x * blockDim.x;
    for (; i < n4; i += stride) {
        float4 v = ((const float4*)src)[i];
        __half2 h0 = __floats2half2_rn(v.x, v.y);
        __half2 h1 = __floats2half2_rn(v.z, v.w);
        ((uint2*)dst)[i] = make_uint2(*(uint32_t*)&h0, *(uint32_t*)&h1);
    }
}

// ================= grouped GEMM (fp16 mma.sync + ldmatrix, 3-stage) ======
// IS_FC:  g_h[off+r,:] = gelu( g_xg[off+r,:] @ wfc[e] )
// !IS_FC: out[tok,:]  += gate * ( g_h[off+r,:] @ wproj[e] )
template <bool IS_FC>
__global__ __launch_bounds__(256, 2)
void moe_gemm(const __half* __restrict__ wsrc, float* __restrict__ out) {
    const int e    = blockIdx.z;
    const int cnt  = g_count[e];
    const int row0 = blockIdx.y * BM;
    if (row0 >= cnt) return;
    const int col0 = blockIdx.x * BN;
    const int off  = g_offset[e];
    const int KDIM = IS_FC ? H_DIM : I_DIM;
    const int NDIM = IS_FC ? I_DIM : H_DIM;
    const int NKB  = KDIM / BK;

    extern __shared__ char sm[];
    const uint32_t smb = smem_u32(sm);

    const int tid  = threadIdx.x;
    const int warp = tid >> 5;
    const int lane = tid & 31;

    // ---- staging maps (cp.async, 4x 16B per thread per stage) ----
    const int arow = tid >> 1;               // 0..127
    const int ahc  = (tid & 1) * 16;         // half-offset within row: 0 or 16
    int ga = row0 + arow; if (ga >= cnt) ga = cnt - 1;
    const __half* aSrc = (IS_FC ? g_xg : g_h) + (size_t)(off + ga) * KDIM + ahc;
    const int brow = tid >> 3;               // 0..31
    const int bhc  = (tid & 7) * 16;         // 0..112 halves
    const __half* bSrc = wsrc + (size_t)e * H_DIM * I_DIM
                       + (size_t)brow * NDIM + col0 + bhc;

    uint32_t aDst[NST], bDst[NST];
#pragma unroll
    for (int s = 0; s < NST; s++) {
        aDst[s] = smb + s * STG + arow * AROW_B + ahc * 2;
        bDst[s] = smb + s * STG + ABYTES + brow * BROW_B + bhc * 2;
    }

#define ISSUE(kb_, st_) do { \
    const __half* as_ = aSrc + (kb_) * BK; \
    cp16(aDst[st_], as_); cp16(aDst[st_] + 16, as_ + 8); \
    const __half* bs_ = bSrc + (size_t)(kb_) * BK * NDIM; \
    cp16(bDst[st_], bs_); cp16(bDst[st_] + 16, bs_ + 8); \
    } while (0)

    // ---- compute maps ----
    const int wm = warp >> 2;        // 0..1 : 64-row warp tile
    const int wn = warp & 3;         // 0..3 : 32-col warp tile
    const int g  = lane >> 2;        // 0..7
    const int t  = lane & 3;         // 0..3

    // ldmatrix lane addressing (offsets within stage)
    const int lrow = lane & 15;
    const int lsel = lane >> 4;      // 0/1
    // A: row = wm*64 + mt*16 + lrow ; khalf = k0 + lsel*8
    const uint32_t aLdBase = (wm * 64 + lrow) * AROW_B + lsel * 16;
    // B: krow = k0 + lrow ; nhalf = wn*32 + half*16 + lsel*8
    const uint32_t bLdBase = ABYTES + lrow * BROW_B + (wn * 32 + lsel * 8) * 2;

    float acc[4][4][4];
#pragma unroll
    for (int mt = 0; mt < 4; mt++)
#pragma unroll
        for (int nt = 0; nt < 4; nt++)
#pragma unroll
            for (int r = 0; r < 4; r++) acc[mt][nt][r] = 0.f;

    ISSUE(0, 0); cp_commit();
    ISSUE(1, 1); cp_commit();

#pragma unroll 1
    for (int kb = 0; kb < NKB; kb++) {
        cp_wait1();
        __syncthreads();
        const int st = kb % NST;
        if (kb + 2 < NKB) ISSUE(kb + 2, (kb + 2) % NST);
        cp_commit();

        const uint32_t stb = smb + st * STG;
#pragma unroll
        for (int ks = 0; ks < 2; ks++) {   // two K16 sub-steps per stage
            const int k0 = ks * 16;
            unsigned afr[4][4], bfr[2][4];
#pragma unroll
            for (int mt = 0; mt < 4; mt++)
                ldsm_x4(afr[mt], stb + aLdBase + mt * 16 * AROW_B + k0 * 2);
#pragma unroll
            for (int h = 0; h < 2; h++)
                ldsm_x4_t(bfr[h], stb + bLdBase + k0 * BROW_B + h * 32);
#pragma unroll
            for (int mt = 0; mt < 4; mt++) {
#pragma unroll
                for (int nt = 0; nt < 4; nt++)
                    mma_f16(acc[mt][nt], afr[mt], &bfr[nt >> 1][(nt & 1) * 2]);
            }
        }
    }
#undef ISSUE

    // ---- epilogue ----
#pragma unroll
    for (int mt = 0; mt < 4; mt++) {
        const int l0 = wm * 64 + mt * 16 + g;
        const int l1 = l0 + 8;
        const int lr0 = row0 + l0;
        const int lr1 = row0 + l1;
#pragma unroll
        for (int nt = 0; nt < 4; nt++) {
            const int c = col0 + wn * 32 + nt * 8 + 2 * t;
            if (IS_FC) {
                if (lr0 < cnt) {
                    __half2 v = __floats2half2_rn(gelu_exact(acc[mt][nt][0]),
                                                  gelu_exact(acc[mt][nt][1]));
                    *(__half2*)(g_h + (size_t)(off + lr0) * I_DIM + c) = v;
                }
                if (lr1 < cnt) {
                    __half2 v = __floats2half2_rn(gelu_exact(acc[mt][nt][2]),
                                                  gelu_exact(acc[mt][nt][3]));
                    *(__half2*)(g_h + (size_t)(off + lr1) * I_DIM + c) = v;
                }
            } else {
                if (lr0 < cnt) {
                    const float gate = g_gate[e * MAXP + lr0];
                    float* dst = out + (size_t)g_tok[e * MAXP + lr0] * H_DIM + c;
                    atomicAdd(dst,     gate * acc[mt][nt][0]);
                    atomicAdd(dst + 1, gate * acc[mt][nt][1]);
                }
                if (lr1 < cnt) {
                    const float gate = g_gate[e * MAXP + lr1];
                    float* dst = out + (size_t)g_tok[e * MAXP + lr1] * H_DIM + c;
                    atomicAdd(dst,     gate * acc[mt][nt][2]);
                    atomicAdd(dst + 1, gate * acc[mt][nt][3]);
                }
            }
        }
    }
}

// ================= launch =================
extern "C" void kernel_launch(void* const* d_in, const int* in_sizes, int n_in,
                              void* d_out, int out_size) {
    const float* x     = (const float*)d_in[0];
    const float* rw    = (const float*)d_in[1];
    const int*   sel   = (const int*)  d_in[2];
    const float* wfc   = (const float*)d_in[3];
    const float* wproj = (const float*)d_in[4];
    float* out = (float*)d_out;

    cudaFuncSetAttribute(moe_gemm<true>,  cudaFuncAttributeMaxDynamicSharedMemorySize, SMEM_SZ);
    cudaFuncSetAttribute(moe_gemm<false>, cudaFuncAttributeMaxDynamicSharedMemorySize, SMEM_SZ);

    __half* wfcH;  cudaGetSymbolAddress((void**)&wfcH, g_wfc_h);
    __half* wprH;  cudaGetSymbolAddress((void**)&wprH, g_wproj_h);

    cudaMemsetAsync(out, 0, (size_t)T_TOK * H_DIM * sizeof(float));
    route_kernel<<<1, 512>>>(rw, sel);
    gather_kernel<<<MAXP, 256>>>(x);
    convert_kernel<<<2048, 256>>>(wfc,   wfcH, E_NUM * H_DIM * I_DIM / 4);
    convert_kernel<<<2048, 256>>>(wproj, wprH, E_NUM * I_DIM * H_DIM / 4);

    dim3 fc_grid(I_DIM / BN, MAXP / BM, E_NUM);
    moe_gemm<true><<<fc_grid, 256, SMEM_SZ>>>(wfcH, out);

    dim3 pj_grid(H_DIM / BN, MAXP / BM, E_NUM);
    moe_gemm<false><<<pj_grid, 256, SMEM_SZ>>>(wprH, out);
}

// round 6
// speedup vs baseline: 5.7091x; 1.0026x over previous
#include <cuda_runtime.h>
#include <cuda_fp16.h>
#include <math.h>
#include <stdint.h>

#define T_TOK 4096
#define H_DIM 1024
#define I_DIM 2048
#define E_NUM 8
#define K_TOP 2
#define MAXP (T_TOK * K_TOP)

#define BM 128
#define BN 128
#define BK 32                      /* halves per k-stage */
#define AROW_B 80                  /* A smem row stride bytes (64 data + 16 pad) */
#define BROW_B 272                 /* B smem row stride bytes (256 data + 16 pad) */
#define ABYTES (BM * AROW_B)       /* 10240 */
#define BBYTES (BK * BROW_B)       /* 8704  */
#define STG    (ABYTES + BBYTES)   /* 18944 */
#define NST 4
#define SMEM_SZ (NST * STG)        /* 75776 */

// ---- static device scratch ----
__device__ int    g_count[E_NUM];
__device__ int    g_offset[E_NUM];
__device__ int    g_tok [E_NUM * MAXP];
__device__ float  g_gate[E_NUM * MAXP];
__device__ __half g_xg[(size_t)MAXP * H_DIM];               // gathered activations fp16
__device__ __half g_h [(size_t)MAXP * I_DIM];               // gelu(fc) intermediate fp16
__device__ __half g_wfc_h  [(size_t)E_NUM * H_DIM * I_DIM]; // fp16 wfc
__device__ __half g_wproj_h[(size_t)E_NUM * I_DIM * H_DIM]; // fp16 wproj

// ================= helpers =================
__device__ __forceinline__ uint32_t smem_u32(const void* p) {
    uint32_t a;
    asm("{ .reg .u64 t; cvta.to.shared.u64 t, %1; cvt.u32.u64 %0, t; }" : "=r"(a) : "l"(p));
    return a;
}
__device__ __forceinline__ float gelu_exact(float v) {
    return 0.5f * v * (1.0f + erff(v * 0.7071067811865476f));
}
__device__ __forceinline__ void cp16(uint32_t dst, const void* src) {
    asm volatile("cp.async.ca.shared.global [%0], [%1], 16;" :: "r"(dst), "l"(src) : "memory");
}
__device__ __forceinline__ void cp_commit() {
    asm volatile("cp.async.commit_group;" ::: "memory");
}
__device__ __forceinline__ void cp_wait2() {
    asm volatile("cp.async.wait_group 2;" ::: "memory");
}
__device__ __forceinline__ void ldsm_x4(unsigned* r, uint32_t addr) {
    asm volatile("ldmatrix.sync.aligned.m8n8.x4.shared.b16 {%0,%1,%2,%3}, [%4];"
                 : "=r"(r[0]), "=r"(r[1]), "=r"(r[2]), "=r"(r[3]) : "r"(addr));
}
__device__ __forceinline__ void ldsm_x4_t(unsigned* r, uint32_t addr) {
    asm volatile("ldmatrix.sync.aligned.m8n8.x4.trans.shared.b16 {%0,%1,%2,%3}, [%4];"
                 : "=r"(r[0]), "=r"(r[1]), "=r"(r[2]), "=r"(r[3]) : "r"(addr));
}
__device__ __forceinline__ void mma_f16(float* d, const unsigned* a, const unsigned* b) {
    asm volatile(
        "mma.sync.aligned.m16n8k16.row.col.f32.f16.f16.f32 "
        "{%0,%1,%2,%3},{%4,%5,%6,%7},{%8,%9},{%0,%1,%2,%3};"
        : "+f"(d[0]), "+f"(d[1]), "+f"(d[2]), "+f"(d[3])
        : "r"(a[0]), "r"(a[1]), "r"(a[2]), "r"(a[3]),
          "r"(b[0]), "r"(b[1]));
}

// ================= routing =================
__global__ void route_kernel(const float* __restrict__ rw,
                             const int*   __restrict__ sel) {
    __shared__ int sc[E_NUM];
    int tid = threadIdx.x;
    if (tid < E_NUM) sc[tid] = 0;
    __syncthreads();
    for (int p = tid; p < T_TOK * K_TOP; p += blockDim.x) {
        int e = sel[p];
        int slot = atomicAdd(&sc[e], 1);
        g_tok [e * MAXP + slot] = p / K_TOP;
        g_gate[e * MAXP + slot] = rw[p];
    }
    __syncthreads();
    if (tid == 0) {
        int off = 0;
        for (int e = 0; e < E_NUM; e++) {
            g_count[e]  = sc[e];
            g_offset[e] = off;
            off += sc[e];
        }
    }
}

// ================= gather activations -> fp16 =================
__global__ void gather_kernel(const float* __restrict__ x) {
    int r = blockIdx.x;
    int e = 0;
#pragma unroll
    for (int i = 0; i < E_NUM; i++)
        if (r >= g_offset[i] + g_count[i]) e = i + 1;
    int tok = g_tok[e * MAXP + (r - g_offset[e])];
    const float4* src = (const float4*)(x + (size_t)tok * H_DIM);
    float4 v = src[threadIdx.x];
    __half2 h0 = __floats2half2_rn(v.x, v.y);
    __half2 h1 = __floats2half2_rn(v.z, v.w);
    uint2 pk = make_uint2(*(uint32_t*)&h0, *(uint32_t*)&h1);
    ((uint2*)(g_xg + (size_t)r * H_DIM))[threadIdx.x] = pk;
}

// ================= fused weight convert -> fp16 (both weights) =========
__global__ void convert_both_kernel(const float* __restrict__ wfc,
                                    const float* __restrict__ wproj,
                                    __half* __restrict__ wfcH,
                                    __half* __restrict__ wprH) {
    const int n4 = E_NUM * H_DIM * I_DIM / 4;   // per tensor
    int i = blockIdx.x * blockDim.x + threadIdx.x;
    const int stride = gridDim.x * blockDim.x;
    for (; i < n4; i += stride) {
        float4 a = ((const float4*)wfc)[i];
        float4 b = ((const float4*)wproj)[i];
        __half2 a0 = __floats2half2_rn(a.x, a.y);
        __half2 a1 = __floats2half2_rn(a.z, a.w);
        __half2 b0 = __floats2half2_rn(b.x, b.y);
        __half2 b1 = __floats2half2_rn(b.z, b.w);
        ((uint2*)wfcH)[i] = make_uint2(*(uint32_t*)&a0, *(uint32_t*)&a1);
        ((uint2*)wprH)[i] = make_uint2(*(uint32_t*)&b0, *(uint32_t*)&b1);
    }
}

// ================= grouped GEMM (fp16 mma.sync + ldmatrix, 4-stage) ======
// IS_FC:  g_h[off+r,:] = gelu( g_xg[off+r,:] @ wfc[e] )
// !IS_FC: out[tok,:]  += gate * ( g_h[off+r,:] @ wproj[e] )
template <bool IS_FC>
__global__ __launch_bounds__(256, 2)
void moe_gemm(const __half* __restrict__ wsrc, float* __restrict__ out) {
    const int e    = blockIdx.z;
    const int cnt  = g_count[e];
    const int row0 = blockIdx.y * BM;
    if (row0 >= cnt) return;
    const int col0 = blockIdx.x * BN;
    const int off  = g_offset[e];
    const int KDIM = IS_FC ? H_DIM : I_DIM;
    const int NDIM = IS_FC ? I_DIM : H_DIM;
    const int NKB  = KDIM / BK;

    extern __shared__ char sm[];
    const uint32_t smb = smem_u32(sm);

    const int tid  = threadIdx.x;
    const int warp = tid >> 5;
    const int lane = tid & 31;

    // ---- staging maps (cp.async, 4x 16B per thread per stage) ----
    const int arow = tid >> 1;               // 0..127
    const int ahc  = (tid & 1) * 16;         // half-offset within row: 0 or 16
    int ga = row0 + arow; if (ga >= cnt) ga = cnt - 1;
    const __half* aSrc = (IS_FC ? g_xg : g_h) + (size_t)(off + ga) * KDIM + ahc;
    const int brow = tid >> 3;               // 0..31
    const int bhc  = (tid & 7) * 16;         // 0..112 halves
    const __half* bSrc = wsrc + (size_t)e * H_DIM * I_DIM
                       + (size_t)brow * NDIM + col0 + bhc;

    uint32_t aDst[NST], bDst[NST];
#pragma unroll
    for (int s = 0; s < NST; s++) {
        aDst[s] = smb + s * STG + arow * AROW_B + ahc * 2;
        bDst[s] = smb + s * STG + ABYTES + brow * BROW_B + bhc * 2;
    }

#define ISSUE(kb_, st_) do { \
    const __half* as_ = aSrc + (kb_) * BK; \
    cp16(aDst[st_], as_); cp16(aDst[st_] + 16, as_ + 8); \
    const __half* bs_ = bSrc + (size_t)(kb_) * BK * NDIM; \
    cp16(bDst[st_], bs_); cp16(bDst[st_] + 16, bs_ + 8); \
    } while (0)

    // ---- compute maps ----
    const int wm = warp >> 2;        // 0..1 : 64-row warp tile
    const int wn = warp & 3;         // 0..3 : 32-col warp tile
    const int g  = lane >> 2;        // 0..7
    const int t  = lane & 3;         // 0..3

    const int lrow = lane & 15;
    const int lsel = lane >> 4;      // 0/1
    const uint32_t aLdBase = (wm * 64 + lrow) * AROW_B + lsel * 16;
    const uint32_t bLdBase = ABYTES + lrow * BROW_B + (wn * 32 + lsel * 8) * 2;

    float acc[4][4][4];
#pragma unroll
    for (int mt = 0; mt < 4; mt++)
#pragma unroll
        for (int nt = 0; nt < 4; nt++)
#pragma unroll
            for (int r = 0; r < 4; r++) acc[mt][nt][r] = 0.f;

    // prologue: 3 stages in flight
    ISSUE(0, 0); cp_commit();
    ISSUE(1, 1); cp_commit();
    ISSUE(2, 2); cp_commit();

#pragma unroll 1
    for (int kb = 0; kb < NKB; kb++) {
        cp_wait2();
        __syncthreads();
        const int st = kb & 3;
        if (kb + 3 < NKB) ISSUE(kb + 3, (kb + 3) & 3);
        cp_commit();

        const uint32_t stb = smb + st * STG;
#pragma unroll
        for (int ks = 0; ks < 2; ks++) {   // two K16 sub-steps per stage
            const int k0 = ks * 16;
            unsigned afr[4][4], bfr[2][4];
#pragma unroll
            for (int h = 0; h < 2; h++)
                ldsm_x4_t(bfr[h], stb + bLdBase + k0 * BROW_B + h * 32);
#pragma unroll
            for (int mt = 0; mt < 4; mt++)
                ldsm_x4(afr[mt], stb + aLdBase + mt * 16 * AROW_B + k0 * 2);
#pragma unroll
            for (int mt = 0; mt < 4; mt++) {
#pragma unroll
                for (int nt = 0; nt < 4; nt++)
                    mma_f16(acc[mt][nt], afr[mt], &bfr[nt >> 1][(nt & 1) * 2]);
            }
        }
    }
#undef ISSUE

    // ---- epilogue ----
#pragma unroll
    for (int mt = 0; mt < 4; mt++) {
        const int l0 = wm * 64 + mt * 16 + g;
        const int l1 = l0 + 8;
        const int lr0 = row0 + l0;
        const int lr1 = row0 + l1;
#pragma unroll
        for (int nt = 0; nt < 4; nt++) {
            const int c = col0 + wn * 32 + nt * 8 + 2 * t;
            if (IS_FC) {
                if (lr0 < cnt) {
                    __half2 v = __floats2half2_rn(gelu_exact(acc[mt][nt][0]),
                                                  gelu_exact(acc[mt][nt][1]));
                    *(__half2*)(g_h + (size_t)(off + lr0) * I_DIM + c) = v;
                }
                if (lr1 < cnt) {
                    __half2 v = __floats2half2_rn(gelu_exact(acc[mt][nt][2]),
                                                  gelu_exact(acc[mt][nt][3]));
                    *(__half2*)(g_h + (size_t)(off + lr1) * I_DIM + c) = v;
                }
            } else {
                if (lr0 < cnt) {
                    const float gate = g_gate[e * MAXP + lr0];
                    float* dst = out + (size_t)g_tok[e * MAXP + lr0] * H_DIM + c;
                    atomicAdd(dst,     gate * acc[mt][nt][0]);
                    atomicAdd(dst + 1, gate * acc[mt][nt][1]);
                }
                if (lr1 < cnt) {
                    const float gate = g_gate[e * MAXP + lr1];
                    float* dst = out + (size_t)g_tok[e * MAXP + lr1] * H_DIM + c;
                    atomicAdd(dst,     gate * acc[mt][nt][2]);
                    atomicAdd(dst + 1, gate * acc[mt][nt][3]);
                }
            }
        }
    }
}

// ================= launch =================
extern "C" void kernel_launch(void* const* d_in, const int* in_sizes, int n_in,
                              void* d_out, int out_size) {
    const float* x     = (const float*)d_in[0];
    const float* rw    = (const float*)d_in[1];
    const int*   sel   = (const int*)  d_in[2];
    const float* wfc   = (const float*)d_in[3];
    const float* wproj = (const float*)d_in[4];
    float* out = (float*)d_out;

    cudaFuncSetAttribute(moe_gemm<true>,  cudaFuncAttributeMaxDynamicSharedMemorySize, SMEM_SZ);
    cudaFuncSetAttribute(moe_gemm<false>, cudaFuncAttributeMaxDynamicSharedMemorySize, SMEM_SZ);

    __half* wfcH;  cudaGetSymbolAddress((void**)&wfcH, g_wfc_h);
    __half* wprH;  cudaGetSymbolAddress((void**)&wprH, g_wproj_h);

    cudaMemsetAsync(out, 0, (size_t)T_TOK * H_DIM * sizeof(float));
    convert_both_kernel<<<1184, 256>>>(wfc, wproj, wfcH, wprH);
    route_kernel<<<1, 512>>>(rw, sel);
    gather_kernel<<<MAXP, 256>>>(x);

    dim3 fc_grid(I_DIM / BN, MAXP / BM, E_NUM);
    moe_gemm<true><<<fc_grid, 256, SMEM_SZ>>>(wfcH, out);

    dim3 pj_grid(H_DIM / BN, MAXP / BM, E_NUM);
    moe_gemm<false><<<pj_grid, 256, SMEM_SZ>>>(wprH, out);
}